// round 10
// baseline (speedup 1.0000x reference)
#include <cuda_runtime.h>

// All-pairs N-body gravity — scalar/packed MIXED inner loop.
// Evidence from 9 rounds: scalar form is issue-bound (16.3 slot-equiv/group:
// 12 fma-class + MUFU's ~4-slot dispatch tax); packed f32x2 form is fma-pipe
// bound (each wide op ~rt3 via RF banks -> 18 cyc/group). Blending 2 scalar
// j's + 1 packed j-pair per 4 j's loads both resources to ~15 cyc/group.

#define BLOCK  256
#define IPT    2
#define JCHUNK 64
#define NW     (JCHUNK / 4)   // packed words (one per 4-j period)
#define EPS2   0.0001f        // SOFTENING^2

typedef unsigned long long u64;

__device__ __forceinline__ u64 pack2(float lo, float hi) {
    u64 r;
    asm("mov.b64 %0, {%1, %2};" : "=l"(r)
        : "r"(__float_as_uint(lo)), "r"(__float_as_uint(hi)));
    return r;
}
__device__ __forceinline__ void unpack2(u64 v, float& lo, float& hi) {
    unsigned a, b;
    asm("mov.b64 {%0, %1}, %2;" : "=r"(a), "=r"(b) : "l"(v));
    lo = __uint_as_float(a);
    hi = __uint_as_float(b);
}
__device__ __forceinline__ u64 f2add(u64 a, u64 b) {
    u64 r; asm("add.rn.f32x2 %0, %1, %2;" : "=l"(r) : "l"(a), "l"(b)); return r;
}
__device__ __forceinline__ u64 f2mul(u64 a, u64 b) {
    u64 r; asm("mul.rn.f32x2 %0, %1, %2;" : "=l"(r) : "l"(a), "l"(b)); return r;
}
__device__ __forceinline__ u64 f2fma(u64 a, u64 b, u64 c) {
    u64 r; asm("fma.rn.f32x2 %0, %1, %2, %3;"
               : "=l"(r) : "l"(a), "l"(b), "l"(c)); return r;
}
__device__ __forceinline__ float rsq_mufu(float x) {
    float r; asm("rsqrt.approx.f32 %0, %1;" : "=f"(r) : "f"(x)); return r;
}

__global__ void zero_out_kernel(float* __restrict__ out, int n) {
    int i = blockIdx.x * blockDim.x + threadIdx.x;
    if (i < n) out[i] = 0.0f;
}

__global__ __launch_bounds__(BLOCK)
void nbody_forces_kernel(const float* __restrict__ pos,
                         const float* __restrict__ mass,
                         float* __restrict__ out) {
    // Per 4-j period w: j = jbase+4w+{0,1} scalar, jbase+4w+{2,3} packed.
    __shared__ float4 sjs[NW * 2];                    // scalar j's {x,y,z,m}
    __shared__ u64 sx[NW], sy[NW], sz[NW], sm[NW];    // packed pair SoA

    const int tid   = threadIdx.x;
    const int i0    = blockIdx.x * (BLOCK * IPT) + tid;
    const int i1    = i0 + BLOCK;
    const int jbase = blockIdx.y * JCHUNK;

    if (tid < JCHUNK) {
        int j = jbase + tid;
        int w = tid >> 2, r = tid & 3;
        float x = pos[3 * j + 0], y = pos[3 * j + 1], z = pos[3 * j + 2];
        float m = mass[j];
        if (r < 2) {
            sjs[2 * w + r] = make_float4(x, y, z, m);
        } else {
            int h = 2 * w + (r - 2);
            ((float*)sx)[h] = x;
            ((float*)sy)[h] = y;
            ((float*)sz)[h] = z;
            ((float*)sm)[h] = m;
        }
    }
    __syncthreads();

    const float x0 = pos[3 * i0 + 0], y0 = pos[3 * i0 + 1], z0 = pos[3 * i0 + 2];
    const float x1 = pos[3 * i1 + 0], y1 = pos[3 * i1 + 1], z1 = pos[3 * i1 + 2];

    const u64 nx0 = pack2(-x0, -x0), ny0 = pack2(-y0, -y0), nz0 = pack2(-z0, -z0);
    const u64 nx1 = pack2(-x1, -x1), ny1 = pack2(-y1, -y1), nz1 = pack2(-z1, -z1);
    const u64 eps22 = pack2(EPS2, EPS2);

    float ax0 = 0.f, ay0 = 0.f, az0 = 0.f;
    float ax1 = 0.f, ay1 = 0.f, az1 = 0.f;
    u64 px0 = 0ull, py0 = 0ull, pz0 = 0ull;   // packed accumulators
    u64 px1 = 0ull, py1 = 0ull, pz1 = 0ull;

#pragma unroll 2
    for (int w = 0; w < NW; ++w) {
        // ---- 2 scalar j's (issue-light on fma pipe) ----
#pragma unroll
        for (int q = 0; q < 2; ++q) {
            const float4 p = sjs[2 * w + q];
            {
                float dx = p.x - x0, dy = p.y - y0, dz = p.z - z0;
                float r2 = fmaf(dx, dx, fmaf(dy, dy, fmaf(dz, dz, EPS2)));
                float inv = rsq_mufu(r2);
                float s = (p.w * inv) * (inv * inv);
                ax0 = fmaf(s, dx, ax0);
                ay0 = fmaf(s, dy, ay0);
                az0 = fmaf(s, dz, az0);
            }
            {
                float dx = p.x - x1, dy = p.y - y1, dz = p.z - z1;
                float r2 = fmaf(dx, dx, fmaf(dy, dy, fmaf(dz, dz, EPS2)));
                float inv = rsq_mufu(r2);
                float s = (p.w * inv) * (inv * inv);
                ax1 = fmaf(s, dx, ax1);
                ay1 = fmaf(s, dy, ay1);
                az1 = fmaf(s, dz, az1);
            }
        }

        // ---- 1 packed j-pair (issue-light overall) ----
        {
            const u64 jx = sx[w], jy = sy[w], jz = sz[w], jm = sm[w];
            // chain 0
            u64 dx = f2add(jx, nx0);
            u64 dy = f2add(jy, ny0);
            u64 dz = f2add(jz, nz0);
            u64 r2 = f2fma(dx, dx, f2fma(dy, dy, f2fma(dz, dz, eps22)));
            float a, b;
            unpack2(r2, a, b);
            u64 inv = pack2(rsq_mufu(a), rsq_mufu(b));
            u64 s = f2mul(jm, f2mul(f2mul(inv, inv), inv));
            px0 = f2fma(s, dx, px0);
            py0 = f2fma(s, dy, py0);
            pz0 = f2fma(s, dz, pz0);
            // chain 1
            dx = f2add(jx, nx1);
            dy = f2add(jy, ny1);
            dz = f2add(jz, nz1);
            r2 = f2fma(dx, dx, f2fma(dy, dy, f2fma(dz, dz, eps22)));
            unpack2(r2, a, b);
            inv = pack2(rsq_mufu(a), rsq_mufu(b));
            s = f2mul(jm, f2mul(f2mul(inv, inv), inv));
            px1 = f2fma(s, dx, px1);
            py1 = f2fma(s, dy, py1);
            pz1 = f2fma(s, dz, pz1);
        }
    }

    float l, h;
    unpack2(px0, l, h); atomicAdd(&out[3 * i0 + 0], ax0 + l + h);
    unpack2(py0, l, h); atomicAdd(&out[3 * i0 + 1], ay0 + l + h);
    unpack2(pz0, l, h); atomicAdd(&out[3 * i0 + 2], az0 + l + h);
    unpack2(px1, l, h); atomicAdd(&out[3 * i1 + 0], ax1 + l + h);
    unpack2(py1, l, h); atomicAdd(&out[3 * i1 + 1], ay1 + l + h);
    unpack2(pz1, l, h); atomicAdd(&out[3 * i1 + 2], az1 + l + h);
}

extern "C" void kernel_launch(void* const* d_in, const int* in_sizes, int n_in,
                              void* d_out, int out_size) {
    const float* pos  = (const float*)d_in[0];   // [N,3] float32
    const float* mass = (const float*)d_in[1];   // [N]   float32
    float* out = (float*)d_out;                  // [N,3] float32

    const int n = in_sizes[0] / 3;               // 8192

    zero_out_kernel<<<(out_size + 255) / 256, 256>>>(out, out_size);

    dim3 grid(n / (BLOCK * IPT), n / JCHUNK);    // 16 x 128 = 2048 CTAs
    nbody_forces_kernel<<<grid, BLOCK>>>(pos, mass, out);
}

// round 11
// speedup vs baseline: 1.0584x; 1.0584x over previous
#include <cuda_runtime.h>

// All-pairs N-body gravity — best-measured inner loop (R5: packed f32x2,
// IPT=2, BLOCK=256) + two overhead cuts:
//   1. zero_out kernel replaced by a cudaMemsetAsync graph node (DMA, no SM
//      launch) — the zero kernel cost ~2.5-3.4us of every replay.
//   2. JCHUNK=64 -> 2048 CTAs for smoother waves (R7 evidence).
// Ten rounds of evidence say the inner loop is at its issue+fma-pipe floor
// (~36us kernel); remaining win is graph/launch overhead.

#define BLOCK  256
#define IPT    2
#define JCHUNK 64
#define JP     (JCHUNK / 2)
#define EPS2   0.0001f   // SOFTENING^2

typedef unsigned long long u64;

__device__ __forceinline__ u64 pack2(float lo, float hi) {
    u64 r;
    asm("mov.b64 %0, {%1, %2};" : "=l"(r)
        : "r"(__float_as_uint(lo)), "r"(__float_as_uint(hi)));
    return r;
}
__device__ __forceinline__ void unpack2(u64 v, float& lo, float& hi) {
    unsigned a, b;
    asm("mov.b64 {%0, %1}, %2;" : "=r"(a), "=r"(b) : "l"(v));
    lo = __uint_as_float(a);
    hi = __uint_as_float(b);
}
__device__ __forceinline__ u64 f2add(u64 a, u64 b) {
    u64 r; asm("add.rn.f32x2 %0, %1, %2;" : "=l"(r) : "l"(a), "l"(b)); return r;
}
__device__ __forceinline__ u64 f2mul(u64 a, u64 b) {
    u64 r; asm("mul.rn.f32x2 %0, %1, %2;" : "=l"(r) : "l"(a), "l"(b)); return r;
}
__device__ __forceinline__ u64 f2fma(u64 a, u64 b, u64 c) {
    u64 r; asm("fma.rn.f32x2 %0, %1, %2, %3;"
               : "=l"(r) : "l"(a), "l"(b), "l"(c)); return r;
}
__device__ __forceinline__ float rsq_mufu(float x) {
    float r; asm("rsqrt.approx.f32 %0, %1;" : "=f"(r) : "f"(x)); return r;
}

__global__ __launch_bounds__(BLOCK)
void nbody_forces_kernel(const float* __restrict__ pos,
                         const float* __restrict__ mass,
                         float* __restrict__ out) {
    // Pair-packed SoA: word t holds bodies {jbase+2t, jbase+2t+1}.
    __shared__ u64 sx[JP], sy[JP], sz[JP], sm[JP];

    const int i0    = blockIdx.x * (BLOCK * IPT) + threadIdx.x;
    const int i1    = i0 + BLOCK;
    const int jbase = blockIdx.y * JCHUNK;

    if (threadIdx.x < JCHUNK) {
        int t = threadIdx.x;
        int j = jbase + t;
        ((float*)sx)[t] = pos[3 * j + 0];
        ((float*)sy)[t] = pos[3 * j + 1];
        ((float*)sz)[t] = pos[3 * j + 2];
        ((float*)sm)[t] = mass[j];
    }
    __syncthreads();

    const u64 nx0 = pack2(-pos[3 * i0 + 0], -pos[3 * i0 + 0]);
    const u64 ny0 = pack2(-pos[3 * i0 + 1], -pos[3 * i0 + 1]);
    const u64 nz0 = pack2(-pos[3 * i0 + 2], -pos[3 * i0 + 2]);
    const u64 nx1 = pack2(-pos[3 * i1 + 0], -pos[3 * i1 + 0]);
    const u64 ny1 = pack2(-pos[3 * i1 + 1], -pos[3 * i1 + 1]);
    const u64 nz1 = pack2(-pos[3 * i1 + 2], -pos[3 * i1 + 2]);
    const u64 eps22 = pack2(EPS2, EPS2);

    u64 ax0 = 0ull, ay0 = 0ull, az0 = 0ull;
    u64 ax1 = 0ull, ay1 = 0ull, az1 = 0ull;

#pragma unroll 4
    for (int t = 0; t < JP; ++t) {
        const u64 px = sx[t];              // LDS.64 broadcast feeds 4 pairs
        const u64 py = sy[t];
        const u64 pz = sz[t];
        const u64 pm = sm[t];

        // chain 0
        u64 dx0 = f2add(px, nx0);
        u64 dy0 = f2add(py, ny0);
        u64 dz0 = f2add(pz, nz0);
        // chain 1 (independent)
        u64 dx1 = f2add(px, nx1);
        u64 dy1 = f2add(py, ny1);
        u64 dz1 = f2add(pz, nz1);

        u64 r20 = f2fma(dx0, dx0, f2fma(dy0, dy0, f2fma(dz0, dz0, eps22)));
        u64 r21 = f2fma(dx1, dx1, f2fma(dy1, dy1, f2fma(dz1, dz1, eps22)));

        float a, b;
        unpack2(r20, a, b);
        u64 inv0 = pack2(rsq_mufu(a), rsq_mufu(b));
        unpack2(r21, a, b);
        u64 inv1 = pack2(rsq_mufu(a), rsq_mufu(b));

        u64 s0 = f2mul(pm, f2mul(f2mul(inv0, inv0), inv0));
        u64 s1 = f2mul(pm, f2mul(f2mul(inv1, inv1), inv1));

        ax0 = f2fma(s0, dx0, ax0);
        ay0 = f2fma(s0, dy0, ay0);
        az0 = f2fma(s0, dz0, az0);
        ax1 = f2fma(s1, dx1, ax1);
        ay1 = f2fma(s1, dy1, ay1);
        az1 = f2fma(s1, dz1, az1);
    }

    float l, h;
    unpack2(ax0, l, h); atomicAdd(&out[3 * i0 + 0], l + h);
    unpack2(ay0, l, h); atomicAdd(&out[3 * i0 + 1], l + h);
    unpack2(az0, l, h); atomicAdd(&out[3 * i0 + 2], l + h);
    unpack2(ax1, l, h); atomicAdd(&out[3 * i1 + 0], l + h);
    unpack2(ay1, l, h); atomicAdd(&out[3 * i1 + 1], l + h);
    unpack2(az1, l, h); atomicAdd(&out[3 * i1 + 2], l + h);
}

extern "C" void kernel_launch(void* const* d_in, const int* in_sizes, int n_in,
                              void* d_out, int out_size) {
    const float* pos  = (const float*)d_in[0];   // [N,3] float32
    const float* mass = (const float*)d_in[1];   // [N]   float32
    float* out = (float*)d_out;                  // [N,3] float32

    const int n = in_sizes[0] / 3;               // 8192

    // Zero via DMA memset node (graph-capturable, no SM launch) — the
    // dedicated zero kernel cost ~2.5-3.4us of every graph replay.
    cudaMemsetAsync(out, 0, (size_t)out_size * sizeof(float), 0);

    dim3 grid(n / (BLOCK * IPT), n / JCHUNK);    // 16 x 128 = 2048 CTAs
    nbody_forces_kernel<<<grid, BLOCK>>>(pos, mass, out);
}